// round 10
// baseline (speedup 1.0000x reference)
#include <cuda_runtime.h>

// Problem constants (fixed by setup_inputs)
#define BS   8
#define NA   128
#define NC   256
#define ZZ   8
#define NT   3
#define NET  9
#define NETASK (BS*NC*3)   // 6144 edge tasks
#define NNODE  (BS*NA)     // 1024 node tasks
#define NTASKS (NETASK + NNODE)  // 7168
#define OUT_LOGPI (BS*NC*ZZ*ZZ*ZZ)   // 1048576

typedef unsigned long long u64;

// ---------------- device scratch (no allocations allowed) ----------------
__device__ __align__(16) float g_nf[NNODE*ZZ];
__device__ __align__(16) float g_ef[NETASK*64];
__device__ int g_ecnt[NET];          // zero at load; re-zeroed by assemble
__device__ int g_ncnt[NT];
__device__ int g_ebucket[NET*NETASK];   // task id
__device__ int g_eoff[NET*NETASK];      // precomputed edge_enc offset
__device__ int g_nbucket[NT*NNODE];     // node id
__device__ int g_noff[NT*NNODE];        // precomputed node_enc offset

static __device__ __forceinline__ int clampi(int v, int lo, int hi) {
    return v < lo ? lo : (v > hi ? hi : v);
}

// ---------------- packed f32x2 helpers (FFMA2) ----------------
static __device__ __forceinline__ u64 pack2(float a, float b) {
    u64 r; asm("mov.b64 %0, {%1, %2};" : "=l"(r) : "f"(a), "f"(b)); return r;
}
static __device__ __forceinline__ void unpack2(u64 v, float& a, float& b) {
    asm("mov.b64 {%0, %1}, %2;" : "=f"(a), "=f"(b) : "l"(v));
}
static __device__ __forceinline__ void ffma2(u64& d, u64 a, u64 b) {
    asm("fma.rn.f32x2 %0, %1, %2, %0;" : "+l"(d) : "l"(a), "l"(b));
}
static __device__ __forceinline__ void prefetchL2(const void* p) {
    asm volatile("prefetch.global.L2 [%0];" :: "l"(p));
}

// ---------------- kernel: bin tasks; trigger PDL, then prefetch ------------
// grid 28 x 256: one task per thread.
__global__ __launch_bounds__(256) void bin_tasks_kernel(
    const int* __restrict__ types, const int* __restrict__ cni,
    const float* __restrict__ node_enc, const float* __restrict__ edge_enc,
    const float* __restrict__ eW0, const float* __restrict__ eW1,
    const float* __restrict__ eW2,
    const float* __restrict__ nW0, const float* __restrict__ nW1)
{
    __shared__ int sT[NNODE];
    __shared__ int h[12];
    __shared__ int basev[12];
    int tid = threadIdx.x;
    int t = blockIdx.x * 256 + tid;

    {
        int4 v = ((const int4*)types)[tid];
        ((int4*)sT)[tid] = v;
    }
    if (tid < 12) h[tid] = 0;
    __syncthreads();

    int bk = -1, val = 0, off = 0, pos = 0;
    const float* pfrow = 0;
    if (t < NETASK) {
        int b   = t / (NC*3);
        int rem = t - b*(NC*3);
        int c   = rem / 3;
        int p   = rem - 3*c;              // 0->(0,1) 1->(0,2) 2->(1,2)
        int a0  = (p == 2) ? 1 : 0;
        int a1  = (p == 0) ? 1 : 2;
        int i = clampi(cni[(b*NC + c)*3 + a0], 0, NA-1);
        int j = clampi(cni[(b*NC + c)*3 + a1], 0, NA-1);
        int ti = clampi(sT[b*NA + i], 0, NT-1);
        int tj = clampi(sT[b*NA + j], 0, NT-1);
        bk  = tj*3 + ti;                  // emask: pa==type[j], pb==type[i]
        val = t;
        off = ((b*NA + i)*NA + j) * 64;
        pfrow = edge_enc + (size_t)off;
    } else if (t < NTASKS) {
        int nn = t - NETASK;
        bk  = 9 + clampi(sT[nn], 0, NT-1);
        val = nn;
        off = nn * 64;
        pfrow = node_enc + (size_t)off;
    }
    if (bk >= 0) pos = atomicAdd(&h[bk], 1);
    __syncthreads();
    if (tid < 12 && h[tid] > 0) {
        basev[tid] = (tid < 9) ? atomicAdd(&g_ecnt[tid], h[tid])
                               : atomicAdd(&g_ncnt[tid-9], h[tid]);
    }
    __syncthreads();
    if (bk >= 0) {
        int base = basev[bk];
        if (bk < 9) {
            g_ebucket[bk*NETASK + base + pos] = val;
            g_eoff   [bk*NETASK + base + pos] = off;
        } else {
            g_nbucket[(bk-9)*NNODE + base + pos] = val;
            g_noff   [(bk-9)*NNODE + base + pos] = off;
        }
    }
    // publish, release mlp early; prefetch drain overlaps mlp launch/prologue
    __threadfence();
    cudaTriggerProgrammaticLaunchCompletion();

    // warm L2: this task's 256B input row
    if (bk >= 0) { prefetchL2(pfrow); prefetchL2(pfrow + 32); }
    // warm L2: edge weights (3 arrays x 2304 x 256B chunks)
    if (t < 6912) {
        int arr = t / 2304, ch = t - arr*2304;
        const float* w = (arr == 0) ? eW0 : (arr == 1) ? eW1 : eW2;
        const float* p = w + (size_t)ch*64;
        prefetchL2(p); prefetchL2(p + 32);
    }
    // warm L2: node weights (2 arrays x 192 x 256B chunks)
    if (t < 384) {
        int arr = t / 192, ch = t - arr*192;
        const float* w = (arr == 0) ? nW0 : nW1;
        const float* p = w + (size_t)ch*64;
        prefetchL2(p); prefetchL2(p + 32);
    }
}

// ---------------- 32x64 @ 64x64 layer, 256 thr, 2 rows x 4 cols/thread ----
static __device__ __forceinline__ void layer64(const float* __restrict__ sIn,
                                               const float* __restrict__ sW,
                                               const float* __restrict__ sb,
                                               int r0, int colb, u64 acc[4]) {
    ulonglong2 bv = *(const ulonglong2*)(sb + colb);
    acc[0] = bv.x; acc[1] = bv.y; acc[2] = bv.x; acc[3] = bv.y;
    const float* in0 = sIn + r0*68;
    const float* in1 = sIn + (r0+4)*68;
    #pragma unroll
    for (int d0 = 0; d0 < 64; d0 += 4) {
        float4 x0 = *(const float4*)(in0 + d0);
        float4 x1 = *(const float4*)(in1 + d0);
        {
            ulonglong2 w = *(const ulonglong2*)(sW + (d0+0)*64 + colb);
            u64 a0 = pack2(x0.x, x0.x), a1 = pack2(x1.x, x1.x);
            ffma2(acc[0], a0, w.x); ffma2(acc[1], a0, w.y);
            ffma2(acc[2], a1, w.x); ffma2(acc[3], a1, w.y);
        }
        {
            ulonglong2 w = *(const ulonglong2*)(sW + (d0+1)*64 + colb);
            u64 a0 = pack2(x0.y, x0.y), a1 = pack2(x1.y, x1.y);
            ffma2(acc[0], a0, w.x); ffma2(acc[1], a0, w.y);
            ffma2(acc[2], a1, w.x); ffma2(acc[3], a1, w.y);
        }
        {
            ulonglong2 w = *(const ulonglong2*)(sW + (d0+2)*64 + colb);
            u64 a0 = pack2(x0.z, x0.z), a1 = pack2(x1.z, x1.z);
            ffma2(acc[0], a0, w.x); ffma2(acc[1], a0, w.y);
            ffma2(acc[2], a1, w.x); ffma2(acc[3], a1, w.y);
        }
        {
            ulonglong2 w = *(const ulonglong2*)(sW + (d0+3)*64 + colb);
            u64 a0 = pack2(x0.w, x0.w), a1 = pack2(x1.w, x1.w);
            ffma2(acc[0], a0, w.x); ffma2(acc[1], a0, w.y);
            ffma2(acc[2], a1, w.x); ffma2(acc[3], a1, w.y);
        }
    }
}

static __device__ __forceinline__ void store_relu(float* __restrict__ sOut,
                                                  int r0, int colb, const u64 acc[4]) {
    float a, b, c, d;
    unpack2(acc[0], a, b); unpack2(acc[1], c, d);
    *(float4*)(sOut + r0*68 + colb) =
        make_float4(fmaxf(a,0.f), fmaxf(b,0.f), fmaxf(c,0.f), fmaxf(d,0.f));
    unpack2(acc[2], a, b); unpack2(acc[3], c, d);
    *(float4*)(sOut + (r0+4)*68 + colb) =
        make_float4(fmaxf(a,0.f), fmaxf(b,0.f), fmaxf(c,0.f), fmaxf(d,0.f));
}

// ---------------- MLP kernel: PDL secondary, empty pre-sync prologue -------
__global__ __launch_bounds__(256) void mlp_kernel(
    const float* __restrict__ node_enc, const float* __restrict__ edge_enc,
    const float* __restrict__ nW0, const float* __restrict__ nb0,
    const float* __restrict__ nW1, const float* __restrict__ nb1,
    const float* __restrict__ nW2, const float* __restrict__ nb2,
    const float* __restrict__ eW0, const float* __restrict__ eb0,
    const float* __restrict__ eW1, const float* __restrict__ eb1,
    const float* __restrict__ eW2, const float* __restrict__ eb2)
{
    // nothing heavy before the sync: just wait for bin's buckets
    cudaGridDependencySynchronize();

    // ---- role mapping (uniform across threads) ----
    int bid = blockIdx.x;
    int g = -1, chunk = 0, acc = 0, cnt = 0;
    bool isEdge = true;
    #pragma unroll
    for (int t = 0; t < NET; t++) {
        int n = __ldcg(&g_ecnt[t]);
        int c = (n + 31) >> 5;
        if (g < 0 && bid < acc + c) { g = t; chunk = bid - acc; cnt = n; }
        acc += c;
    }
    if (g < 0) {
        isEdge = false;
        int nb = bid - acc; acc = 0;
        #pragma unroll
        for (int t = 0; t < NT; t++) {
            int n = __ldcg(&g_ncnt[t]);
            int c = (n + 31) >> 5;
            if (g < 0 && nb < acc + c) { g = t; chunk = nb - acc; cnt = n; }
            acc += c;
        }
        if (g < 0) return;
    }
    int base  = chunk * 32;
    int ntask = min(32, cnt - base);

    __shared__ __align__(16) float sW[64*64];
    __shared__ __align__(16) float sb0[64], sb1[64], sb2[64];
    __shared__ __align__(16) float sA[32*68];
    __shared__ __align__(16) float sB[32*68];
    __shared__ int s_idx[32];
    __shared__ int s_off[32];

    int tid  = threadIdx.x;
    int warp = tid >> 5, lane = tid & 31;
    int colb = (warp & 1) * 32 + (lane & 7) * 4;
    int r0   = (warp >> 1) * 8 + (lane >> 3);

    const float *W0, *W1, *b0, *b1, *inBase;
    if (isEdge) {
        W0 = eW0 + g*4096; W1 = eW1 + g*4096;
        b0 = eb0 + g*64;   b1 = eb1 + g*64;
        inBase = edge_enc;
        if (tid < 32) {
            s_idx[tid] = __ldcg(&g_ebucket[g*NETASK + base + min(tid, ntask-1)]);
            s_off[tid] = __ldcg(&g_eoff   [g*NETASK + base + min(tid, ntask-1)]);
        }
    } else {
        W0 = nW0 + g*4096; W1 = nW1 + g*4096;
        b0 = nb0 + g*64;   b1 = nb1 + g*64;
        inBase = node_enc;
        if (tid < 32) {
            s_idx[tid] = __ldcg(&g_nbucket[g*NNODE + base + min(tid, ntask-1)]);
            s_off[tid] = __ldcg(&g_noff   [g*NNODE + base + min(tid, ntask-1)]);
        }
    }

    // stage W0 + biases (L2-warm from bin prefetch)
    {
        const float4* w = (const float4*)W0;
        float4* sw = (float4*)sW;
        #pragma unroll
        for (int k = 0; k < 4; k++) sw[tid + 256*k] = w[tid + 256*k];
        if (tid < 64) { sb0[tid] = b0[tid]; sb1[tid] = b1[tid]; }
    }
    __syncthreads();

    // gather inputs (L2-warm), prefetch W1 into regs
    float4 pw[4];
    {
        const float4* w = (const float4*)W1;
        #pragma unroll
        for (int k = 0; k < 4; k++) pw[k] = w[tid + 256*k];
    }
    {
        int s = tid >> 4, q = tid & 15;
        *(float4*)(sA + s*68 + q*4)      = *(const float4*)(inBase + (size_t)s_off[s]    + q*4);
        *(float4*)(sA + (s+16)*68 + q*4) = *(const float4*)(inBase + (size_t)s_off[s+16] + q*4);
    }
    __syncthreads();

    u64 a4[4];
    layer64(sA, sW, sb0, r0, colb, a4);              // layer 0
    __syncthreads();
    store_relu(sB, r0, colb, a4);
    {
        float4* sw = (float4*)sW;
        #pragma unroll
        for (int k = 0; k < 4; k++) sw[tid + 256*k] = pw[k];
    }
    if (isEdge) {
        const float4* w = (const float4*)(eW2 + g*4096);
        #pragma unroll
        for (int k = 0; k < 4; k++) pw[k] = w[tid + 256*k];
        if (tid < 64) sb2[tid] = eb2[g*64 + tid];
    } else {
        if (tid < 128) pw[0] = ((const float4*)(nW2 + g*512))[tid];
        if (tid < 8)   sb2[tid] = nb2[g*8 + tid];
    }
    __syncthreads();

    layer64(sB, sW, sb1, r0, colb, a4);              // layer 1
    __syncthreads();
    store_relu(sA, r0, colb, a4);
    {
        float4* sw = (float4*)sW;
        if (isEdge) {
            #pragma unroll
            for (int k = 0; k < 4; k++) sw[tid + 256*k] = pw[k];
        } else {
            if (tid < 128) sw[tid] = pw[0];
        }
    }
    __syncthreads();

    if (isEdge) {                                     // layer 2 (edge, no relu)
        layer64(sA, sW, sb2, r0, colb, a4);
        float a, b, c, d;
        if (r0 < ntask) {
            unpack2(a4[0], a, b); unpack2(a4[1], c, d);
            *(float4*)(g_ef + (size_t)s_idx[r0]*64 + colb) = make_float4(a, b, c, d);
        }
        if (r0 + 4 < ntask) {
            unpack2(a4[2], a, b); unpack2(a4[3], c, d);
            *(float4*)(g_ef + (size_t)s_idx[r0+4]*64 + colb) = make_float4(a, b, c, d);
        }
    } else {                                          // layer 2 (node, 64->8)
        int row = tid >> 3, col = tid & 7;
        float a = sb2[col];
        const float* in = sA + row*68;
        #pragma unroll 16
        for (int d = 0; d < 64; d++) a += in[d] * sW[d*8 + col];
        if (row < ntask) g_nf[(size_t)s_idx[row]*8 + col] = a;
    }
    __threadfence();
    cudaTriggerProgrammaticLaunchCompletion();
}

// ---------------- kernel: assemble logpi (PDL; z-tail pre-sync) ----------
__global__ __launch_bounds__(256) void assemble_kernel(
    const int* __restrict__ cni, float* __restrict__ out, int writeZ)
{
    int tid = threadIdx.x;
    int sub = tid >> 6;
    int t   = tid & 63;
    int cq  = blockIdx.x * 4 + sub;

    __shared__ float e[4][192];
    __shared__ float nf[4][3][8];

    // PRE-SYNC: z tail (out region untouched by mlp) — tiny, no contention
    if (blockIdx.x == 0 && writeZ) {
        for (int m = tid; m < 512; m += 256) {
            int i = m >> 6, j = (m >> 3) & 7, k = m & 7;
            float* p = out + OUT_LOGPI + (size_t)m*3;
            p[0] = (float)i; p[1] = (float)j; p[2] = (float)k;
        }
    }

    cudaGridDependencySynchronize();

    // post-sync: safe to reset counters for the next replay (mlp grid done)
    if (blockIdx.x == 0) {
        if (tid < NET) g_ecnt[tid] = 0;
        if (tid < NT)  g_ncnt[tid] = 0;
    }

    size_t tbase = (size_t)cq * 192;
    e[sub][t]       = __ldcg(&g_ef[tbase + t]);
    e[sub][t + 64]  = __ldcg(&g_ef[tbase + t + 64]);
    e[sub][t + 128] = __ldcg(&g_ef[tbase + t + 128]);
    if (t < 24) {
        int k = t >> 3, zz = t & 7;
        int b = cq / NC;
        int node = clampi(cni[cq*3 + k], 0, NA-1);
        nf[sub][k][zz] = __ldcg(&g_nf[((size_t)b*NA + node)*8 + zz]);
    }
    __syncthreads();

    int z0 = t >> 3, z1 = t & 7;
    float bse = nf[sub][0][z0] + nf[sub][1][z1] + e[sub][z0*8 + z1];
    float r[8];
    #pragma unroll
    for (int z2 = 0; z2 < 8; z2++)
        r[z2] = bse + nf[sub][2][z2] + e[sub][64 + z0*8 + z2] + e[sub][128 + z1*8 + z2];
    float* op = out + (size_t)cq*512 + t*8;
    *(float4*)op       = make_float4(r[0], r[1], r[2], r[3]);
    *(float4*)(op + 4) = make_float4(r[4], r[5], r[6], r[7]);
}

// ---------------- launch ----------------
extern "C" void kernel_launch(void* const* d_in, const int* in_sizes, int n_in,
                              void* d_out, int out_size) {
    const int*   types    = (const int*)d_in[0];
    const float* node_enc = (const float*)d_in[1];
    const float* edge_enc = (const float*)d_in[2];
    const int*   cni      = (const int*)d_in[4];
    const float* nW0 = (const float*)d_in[6];
    const float* nb0 = (const float*)d_in[7];
    const float* nW1 = (const float*)d_in[8];
    const float* nb1 = (const float*)d_in[9];
    const float* nW2 = (const float*)d_in[10];
    const float* nb2 = (const float*)d_in[11];
    const float* eW0 = (const float*)d_in[12];
    const float* eb0 = (const float*)d_in[13];
    const float* eW1 = (const float*)d_in[14];
    const float* eb1 = (const float*)d_in[15];
    const float* eW2 = (const float*)d_in[16];
    const float* eb2 = (const float*)d_in[17];
    float* out = (float*)d_out;

    int writeZ = (out_size >= OUT_LOGPI + 512*3) ? 1 : 0;

    bin_tasks_kernel<<<28, 256>>>(types, cni, node_enc, edge_enc,
                                  eW0, eW1, eW2, nW0, nW1);

    cudaLaunchAttribute attr[1];
    attr[0].id = cudaLaunchAttributeProgrammaticStreamSerialization;
    attr[0].val.programmaticStreamSerializationAllowed = 1;

    {
        cudaLaunchConfig_t cfg = {};
        cfg.gridDim  = dim3(240, 1, 1);
        cfg.blockDim = dim3(256, 1, 1);
        cfg.stream   = 0;
        cfg.attrs    = attr;
        cfg.numAttrs = 1;
        cudaLaunchKernelEx(&cfg, mlp_kernel, node_enc, edge_enc,
                           nW0, nb0, nW1, nb1, nW2, nb2,
                           eW0, eb0, eW1, eb1, eW2, eb2);
    }
    {
        cudaLaunchConfig_t cfg = {};
        cfg.gridDim  = dim3(BS * NC / 4, 1, 1);
        cfg.blockDim = dim3(256, 1, 1);
        cfg.stream   = 0;
        cfg.attrs    = attr;
        cfg.numAttrs = 1;
        cudaLaunchKernelEx(&cfg, assemble_kernel, cni, out, writeZ);
    }
}

// round 11
// speedup vs baseline: 1.0434x; 1.0434x over previous
#include <cuda_runtime.h>

// Problem constants (fixed by setup_inputs)
#define BS   8
#define NA   128
#define NC   256
#define ZZ   8
#define NT   3
#define NET  9
#define NETASK (BS*NC*3)   // 6144 edge tasks
#define NNODE  (BS*NA)     // 1024 node tasks
#define NTASKS (NETASK + NNODE)  // 7168
#define OUT_LOGPI (BS*NC*ZZ*ZZ*ZZ)   // 1048576
#define ECH 32             // chunks per edge type (capacity 1024)
#define NCH 16             // chunks per node type (capacity 512)
#define MLP_GRID (NET*ECH + NT*NCH)  // 336
#define MLP_SMEM 69632     // dynamic smem bytes

typedef unsigned long long u64;

// ---------------- device scratch (no allocations allowed) ----------------
__device__ __align__(16) float g_nf[NNODE*ZZ];
__device__ __align__(16) float g_ef[NETASK*64];
__device__ int g_ecnt[NET];          // zero at load; re-zeroed by assemble
__device__ int g_ncnt[NT];
__device__ int g_ebucket[NET*NETASK];   // task id
__device__ int g_eoff[NET*NETASK];      // precomputed edge_enc offset
__device__ int g_nbucket[NT*NNODE];     // node id
__device__ int g_noff[NT*NNODE];        // precomputed node_enc offset

static __device__ __forceinline__ int clampi(int v, int lo, int hi) {
    return v < lo ? lo : (v > hi ? hi : v);
}

// ---------------- packed f32x2 helpers (FFMA2) ----------------
static __device__ __forceinline__ u64 pack2(float a, float b) {
    u64 r; asm("mov.b64 %0, {%1, %2};" : "=l"(r) : "f"(a), "f"(b)); return r;
}
static __device__ __forceinline__ void unpack2(u64 v, float& a, float& b) {
    asm("mov.b64 {%0, %1}, %2;" : "=f"(a), "=f"(b) : "l"(v));
}
static __device__ __forceinline__ void ffma2(u64& d, u64 a, u64 b) {
    asm("fma.rn.f32x2 %0, %1, %2, %0;" : "+l"(d) : "l"(a), "l"(b));
}

// ---------------- kernel: bin tasks (lean; no prefetch) --------------------
__global__ __launch_bounds__(256) void bin_tasks_kernel(
    const int* __restrict__ types, const int* __restrict__ cni)
{
    __shared__ int sT[NNODE];
    __shared__ int h[12];
    __shared__ int basev[12];
    int tid = threadIdx.x;
    int t = blockIdx.x * 256 + tid;

    {
        int4 v = ((const int4*)types)[tid];
        ((int4*)sT)[tid] = v;
    }
    if (tid < 12) h[tid] = 0;
    __syncthreads();

    int bk = -1, val = 0, off = 0, pos = 0;
    if (t < NETASK) {
        int b   = t / (NC*3);
        int rem = t - b*(NC*3);
        int c   = rem / 3;
        int p   = rem - 3*c;              // 0->(0,1) 1->(0,2) 2->(1,2)
        int a0  = (p == 2) ? 1 : 0;
        int a1  = (p == 0) ? 1 : 2;
        int i = clampi(cni[(b*NC + c)*3 + a0], 0, NA-1);
        int j = clampi(cni[(b*NC + c)*3 + a1], 0, NA-1);
        int ti = clampi(sT[b*NA + i], 0, NT-1);
        int tj = clampi(sT[b*NA + j], 0, NT-1);
        bk  = tj*3 + ti;                  // emask: pa==type[j], pb==type[i]
        val = t;
        off = ((b*NA + i)*NA + j) * 64;
    } else if (t < NTASKS) {
        int nn = t - NETASK;
        bk  = 9 + clampi(sT[nn], 0, NT-1);
        val = nn;
        off = nn * 64;
    }
    if (bk >= 0) pos = atomicAdd(&h[bk], 1);
    __syncthreads();
    if (tid < 12 && h[tid] > 0) {
        basev[tid] = (tid < 9) ? atomicAdd(&g_ecnt[tid], h[tid])
                               : atomicAdd(&g_ncnt[tid-9], h[tid]);
    }
    __syncthreads();
    if (bk >= 0) {
        int base = basev[bk];
        if (bk < 9) {
            g_ebucket[bk*NETASK + base + pos] = val;
            g_eoff   [bk*NETASK + base + pos] = off;
        } else {
            g_nbucket[(bk-9)*NNODE + base + pos] = val;
            g_noff   [(bk-9)*NNODE + base + pos] = off;
        }
    }
}

// ---------------- 32x64 @ 64x64 layer, 256 thr, 2 rows x 4 cols/thread ----
static __device__ __forceinline__ void layer64(const float* __restrict__ sIn,
                                               const float* __restrict__ sW,
                                               const float* __restrict__ sb,
                                               int r0, int colb, u64 acc[4]) {
    ulonglong2 bv = *(const ulonglong2*)(sb + colb);
    acc[0] = bv.x; acc[1] = bv.y; acc[2] = bv.x; acc[3] = bv.y;
    const float* in0 = sIn + r0*68;
    const float* in1 = sIn + (r0+4)*68;
    #pragma unroll
    for (int d0 = 0; d0 < 64; d0 += 4) {
        float4 x0 = *(const float4*)(in0 + d0);
        float4 x1 = *(const float4*)(in1 + d0);
        {
            ulonglong2 w = *(const ulonglong2*)(sW + (d0+0)*64 + colb);
            u64 a0 = pack2(x0.x, x0.x), a1 = pack2(x1.x, x1.x);
            ffma2(acc[0], a0, w.x); ffma2(acc[1], a0, w.y);
            ffma2(acc[2], a1, w.x); ffma2(acc[3], a1, w.y);
        }
        {
            ulonglong2 w = *(const ulonglong2*)(sW + (d0+1)*64 + colb);
            u64 a0 = pack2(x0.y, x0.y), a1 = pack2(x1.y, x1.y);
            ffma2(acc[0], a0, w.x); ffma2(acc[1], a0, w.y);
            ffma2(acc[2], a1, w.x); ffma2(acc[3], a1, w.y);
        }
        {
            ulonglong2 w = *(const ulonglong2*)(sW + (d0+2)*64 + colb);
            u64 a0 = pack2(x0.z, x0.z), a1 = pack2(x1.z, x1.z);
            ffma2(acc[0], a0, w.x); ffma2(acc[1], a0, w.y);
            ffma2(acc[2], a1, w.x); ffma2(acc[3], a1, w.y);
        }
        {
            ulonglong2 w = *(const ulonglong2*)(sW + (d0+3)*64 + colb);
            u64 a0 = pack2(x0.w, x0.w), a1 = pack2(x1.w, x1.w);
            ffma2(acc[0], a0, w.x); ffma2(acc[1], a0, w.y);
            ffma2(acc[2], a1, w.x); ffma2(acc[3], a1, w.y);
        }
    }
}

static __device__ __forceinline__ void store_relu(float* __restrict__ sOut,
                                                  int r0, int colb, const u64 acc[4]) {
    float a, b, c, d;
    unpack2(acc[0], a, b); unpack2(acc[1], c, d);
    *(float4*)(sOut + r0*68 + colb) =
        make_float4(fmaxf(a,0.f), fmaxf(b,0.f), fmaxf(c,0.f), fmaxf(d,0.f));
    unpack2(acc[2], a, b); unpack2(acc[3], c, d);
    *(float4*)(sOut + (r0+4)*68 + colb) =
        make_float4(fmaxf(a,0.f), fmaxf(b,0.f), fmaxf(c,0.f), fmaxf(d,0.f));
}

// ---------------- MLP: static role map, all weights staged once, 3 syncs ---
__global__ __launch_bounds__(256) void mlp_kernel(
    const float* __restrict__ node_enc, const float* __restrict__ edge_enc,
    const float* __restrict__ nW0, const float* __restrict__ nb0,
    const float* __restrict__ nW1, const float* __restrict__ nb1,
    const float* __restrict__ nW2, const float* __restrict__ nb2,
    const float* __restrict__ eW0, const float* __restrict__ eb0,
    const float* __restrict__ eW1, const float* __restrict__ eb1,
    const float* __restrict__ eW2, const float* __restrict__ eb2)
{
    extern __shared__ __align__(16) float dsm[];
    float* sW0 = dsm;                 // 4096
    float* sW1 = dsm + 4096;          // 4096
    float* sW2 = dsm + 8192;          // 4096
    float* sA  = dsm + 12288;         // 32*68
    float* sB  = dsm + 14464;         // 32*68
    float* sb0 = dsm + 16640;
    float* sb1 = dsm + 16704;
    float* sb2 = dsm + 16768;

    int tid = threadIdx.x, bid = blockIdx.x;

    // static role map: weight staging independent of bin results
    bool isEdge = bid < NET*ECH;
    int g, base;
    if (isEdge) { g = bid >> 5; base = (bid & 31) * 32; }
    else { int nb = bid - NET*ECH; g = nb >> 4; base = (nb & 15) * 32; }

    const float *W0, *W1, *b0, *b1, *inBase;
    if (isEdge) {
        W0 = eW0 + g*4096; W1 = eW1 + g*4096;
        b0 = eb0 + g*64;   b1 = eb1 + g*64;
        inBase = edge_enc;
    } else {
        W0 = nW0 + g*4096; W1 = nW1 + g*4096;
        b0 = nb0 + g*64;   b1 = nb1 + g*64;
        inBase = node_enc;
    }

    // ---- single load front: count, weights, biases, offsets, gather, idx --
    int cnt = isEdge ? __ldcg(&g_ecnt[g]) : __ldcg(&g_ncnt[g]);

    {   // stage W0, W1
        const float4* w0 = (const float4*)W0;
        const float4* w1 = (const float4*)W1;
        float4* s0 = (float4*)sW0; float4* s1 = (float4*)sW1;
        #pragma unroll
        for (int k = 0; k < 4; k++) {
            s0[tid + 256*k] = w0[tid + 256*k];
            s1[tid + 256*k] = w1[tid + 256*k];
        }
    }
    if (isEdge) {   // stage W2 (edge: 4096 floats)
        const float4* w2 = (const float4*)(eW2 + g*4096);
        float4* s2 = (float4*)sW2;
        #pragma unroll
        for (int k = 0; k < 4; k++) s2[tid + 256*k] = w2[tid + 256*k];
    } else if (tid < 128) {   // node W2: 512 floats
        ((float4*)sW2)[tid] = ((const float4*)(nW2 + g*512))[tid];
    }
    if (tid < 64) {
        sb0[tid] = b0[tid];
        sb1[tid] = b1[tid];
        sb2[tid] = isEdge ? eb2[g*64 + tid] : (tid < 8 ? nb2[g*8 + tid] : 0.f);
    }

    // offsets + gather (speculative past cnt: arrays are full-size & 0-init)
    int s = tid >> 4, q = tid & 15;
    int offA, offB;
    if (isEdge) {
        offA = __ldcg(&g_eoff[g*NETASK + base + s]);
        offB = __ldcg(&g_eoff[g*NETASK + base + s + 16]);
    } else {
        offA = __ldcg(&g_noff[g*NNODE + base + s]);
        offB = __ldcg(&g_noff[g*NNODE + base + s + 16]);
    }

    // output indices for this thread's rows (used only under ntask guard)
    int warp = tid >> 5, lane = tid & 31;
    int colb = (warp & 1) * 32 + (lane & 7) * 4;
    int r0   = (warp >> 1) * 8 + (lane >> 3);
    int idx0, idx1;
    if (isEdge) {
        idx0 = __ldcg(&g_ebucket[g*NETASK + base + r0]);
        idx1 = __ldcg(&g_ebucket[g*NETASK + base + r0 + 4]);
    } else {
        idx0 = __ldcg(&g_nbucket[g*NNODE + base + (tid >> 3)]);
        idx1 = 0;
    }

    if (base >= cnt) return;             // empty chunk: uniform exit
    int ntask = min(32, cnt - base);

    *(float4*)(sA + s*68 + q*4)      = *(const float4*)(inBase + (size_t)offA + q*4);
    *(float4*)(sA + (s+16)*68 + q*4) = *(const float4*)(inBase + (size_t)offB + q*4);
    __syncthreads();                                         // sync 1

    u64 a4[4];
    layer64(sA, sW0, sb0, r0, colb, a4);                     // layer 0
    store_relu(sB, r0, colb, a4);
    __syncthreads();                                         // sync 2

    layer64(sB, sW1, sb1, r0, colb, a4);                     // layer 1
    store_relu(sA, r0, colb, a4);
    __syncthreads();                                         // sync 3

    if (isEdge) {                                            // layer 2 (edge)
        layer64(sA, sW2, sb2, r0, colb, a4);
        float a, b, c, d;
        if (r0 < ntask) {
            unpack2(a4[0], a, b); unpack2(a4[1], c, d);
            *(float4*)(g_ef + (size_t)idx0*64 + colb) = make_float4(a, b, c, d);
        }
        if (r0 + 4 < ntask) {
            unpack2(a4[2], a, b); unpack2(a4[3], c, d);
            *(float4*)(g_ef + (size_t)idx1*64 + colb) = make_float4(a, b, c, d);
        }
    } else {                                                 // layer 2 (node)
        int row = tid >> 3, col = tid & 7;
        float a = sb2[col];
        const float* in = sA + row*68;
        #pragma unroll 16
        for (int d = 0; d < 64; d++) a += in[d] * sW2[d*8 + col];
        if (row < ntask) g_nf[(size_t)idx0*8 + col] = a;
    }
    __threadfence();
    cudaTriggerProgrammaticLaunchCompletion();
}

// ---------------- kernel: assemble logpi (PDL; z-tail pre-sync) ----------
__global__ __launch_bounds__(256) void assemble_kernel(
    const int* __restrict__ cni, float* __restrict__ out, int writeZ)
{
    int tid = threadIdx.x;
    int sub = tid >> 6;
    int t   = tid & 63;
    int cq  = blockIdx.x * 4 + sub;

    __shared__ float e[4][192];
    __shared__ float nf[4][3][8];

    if (blockIdx.x == 0 && writeZ) {
        for (int m = tid; m < 512; m += 256) {
            int i = m >> 6, j = (m >> 3) & 7, k = m & 7;
            float* p = out + OUT_LOGPI + (size_t)m*3;
            p[0] = (float)i; p[1] = (float)j; p[2] = (float)k;
        }
    }

    cudaGridDependencySynchronize();

    if (blockIdx.x == 0) {               // reset counters for next replay
        if (tid < NET) g_ecnt[tid] = 0;
        if (tid < NT)  g_ncnt[tid] = 0;
    }

    size_t tbase = (size_t)cq * 192;
    e[sub][t]       = __ldcg(&g_ef[tbase + t]);
    e[sub][t + 64]  = __ldcg(&g_ef[tbase + t + 64]);
    e[sub][t + 128] = __ldcg(&g_ef[tbase + t + 128]);
    if (t < 24) {
        int k = t >> 3, zz = t & 7;
        int b = cq / NC;
        int node = clampi(cni[cq*3 + k], 0, NA-1);
        nf[sub][k][zz] = __ldcg(&g_nf[((size_t)b*NA + node)*8 + zz]);
    }
    __syncthreads();

    int z0 = t >> 3, z1 = t & 7;
    float bse = nf[sub][0][z0] + nf[sub][1][z1] + e[sub][z0*8 + z1];
    float r[8];
    #pragma unroll
    for (int z2 = 0; z2 < 8; z2++)
        r[z2] = bse + nf[sub][2][z2] + e[sub][64 + z0*8 + z2] + e[sub][128 + z1*8 + z2];
    float* op = out + (size_t)cq*512 + t*8;
    *(float4*)op       = make_float4(r[0], r[1], r[2], r[3]);
    *(float4*)(op + 4) = make_float4(r[4], r[5], r[6], r[7]);
}

// ---------------- launch ----------------
extern "C" void kernel_launch(void* const* d_in, const int* in_sizes, int n_in,
                              void* d_out, int out_size) {
    const int*   types    = (const int*)d_in[0];
    const float* node_enc = (const float*)d_in[1];
    const float* edge_enc = (const float*)d_in[2];
    const int*   cni      = (const int*)d_in[4];
    const float* nW0 = (const float*)d_in[6];
    const float* nb0 = (const float*)d_in[7];
    const float* nW1 = (const float*)d_in[8];
    const float* nb1 = (const float*)d_in[9];
    const float* nW2 = (const float*)d_in[10];
    const float* nb2 = (const float*)d_in[11];
    const float* eW0 = (const float*)d_in[12];
    const float* eb0 = (const float*)d_in[13];
    const float* eW1 = (const float*)d_in[14];
    const float* eb1 = (const float*)d_in[15];
    const float* eW2 = (const float*)d_in[16];
    const float* eb2 = (const float*)d_in[17];
    float* out = (float*)d_out;

    int writeZ = (out_size >= OUT_LOGPI + 512*3) ? 1 : 0;

    cudaFuncSetAttribute(mlp_kernel,
                         cudaFuncAttributeMaxDynamicSharedMemorySize, MLP_SMEM);

    // plain launches for bin and mlp (bin->mlp overlap measured harmful 3x)
    bin_tasks_kernel<<<28, 256>>>(types, cni);
    mlp_kernel<<<MLP_GRID, 256, MLP_SMEM>>>(node_enc, edge_enc,
                                            nW0, nb0, nW1, nb1, nW2, nb2,
                                            eW0, eb0, eW1, eb1, eW2, eb2);

    // PDL only on mlp->assemble (pre-sync work is tiny)
    cudaLaunchAttribute attr[1];
    attr[0].id = cudaLaunchAttributeProgrammaticStreamSerialization;
    attr[0].val.programmaticStreamSerializationAllowed = 1;
    cudaLaunchConfig_t cfg = {};
    cfg.gridDim  = dim3(BS * NC / 4, 1, 1);
    cfg.blockDim = dim3(256, 1, 1);
    cfg.stream   = 0;
    cfg.attrs    = attr;
    cfg.numAttrs = 1;
    cudaLaunchKernelEx(&cfg, assemble_kernel, cni, out, writeZ);
}

// round 12
// speedup vs baseline: 1.0578x; 1.0138x over previous
#include <cuda_runtime.h>

// Problem constants (fixed by setup_inputs)
#define BS   8
#define NA   128
#define NC   256
#define ZZ   8
#define NT   3
#define NET  9
#define NETASK (BS*NC*3)   // 6144 edge tasks
#define NNODE  (BS*NA)     // 1024 node tasks
#define NTASKS (NETASK + NNODE)  // 7168
#define OUT_LOGPI (BS*NC*ZZ*ZZ*ZZ)   // 1048576
#define MLP_SMEM 69632     // dynamic smem bytes

typedef unsigned long long u64;

// ---------------- device scratch (no allocations allowed) ----------------
__device__ __align__(16) float g_nf[NNODE*ZZ];
__device__ __align__(16) float g_ef[NETASK*64];
__device__ int g_ecnt[NET];          // zero at load; re-zeroed by assemble
__device__ int g_ncnt[NT];
__device__ int g_ebucket[NET*NETASK];   // task id
__device__ int g_eoff[NET*NETASK];      // precomputed edge_enc offset
__device__ int g_nbucket[NT*NNODE];     // node id
__device__ int g_noff[NT*NNODE];        // precomputed node_enc offset

static __device__ __forceinline__ int clampi(int v, int lo, int hi) {
    return v < lo ? lo : (v > hi ? hi : v);
}

// ---------------- packed f32x2 helpers (FFMA2) ----------------
static __device__ __forceinline__ u64 pack2(float a, float b) {
    u64 r; asm("mov.b64 %0, {%1, %2};" : "=l"(r) : "f"(a), "f"(b)); return r;
}
static __device__ __forceinline__ void unpack2(u64 v, float& a, float& b) {
    asm("mov.b64 {%0, %1}, %2;" : "=f"(a), "=f"(b) : "l"(v));
}
static __device__ __forceinline__ void ffma2(u64& d, u64 a, u64 b) {
    asm("fma.rn.f32x2 %0, %1, %2, %0;" : "+l"(d) : "l"(a), "l"(b));
}

// ---------------- kernel: bin tasks (lean; no prefetch) --------------------
__global__ __launch_bounds__(256) void bin_tasks_kernel(
    const int* __restrict__ types, const int* __restrict__ cni)
{
    __shared__ int sT[NNODE];
    __shared__ int h[12];
    __shared__ int basev[12];
    int tid = threadIdx.x;
    int t = blockIdx.x * 256 + tid;

    {
        int4 v = ((const int4*)types)[tid];
        ((int4*)sT)[tid] = v;
    }
    if (tid < 12) h[tid] = 0;
    __syncthreads();

    int bk = -1, val = 0, off = 0, pos = 0;
    if (t < NETASK) {
        int b   = t / (NC*3);
        int rem = t - b*(NC*3);
        int c   = rem / 3;
        int p   = rem - 3*c;              // 0->(0,1) 1->(0,2) 2->(1,2)
        int a0  = (p == 2) ? 1 : 0;
        int a1  = (p == 0) ? 1 : 2;
        int i = clampi(cni[(b*NC + c)*3 + a0], 0, NA-1);
        int j = clampi(cni[(b*NC + c)*3 + a1], 0, NA-1);
        int ti = clampi(sT[b*NA + i], 0, NT-1);
        int tj = clampi(sT[b*NA + j], 0, NT-1);
        bk  = tj*3 + ti;                  // emask: pa==type[j], pb==type[i]
        val = t;
        off = ((b*NA + i)*NA + j) * 64;
    } else if (t < NTASKS) {
        int nn = t - NETASK;
        bk  = 9 + clampi(sT[nn], 0, NT-1);
        val = nn;
        off = nn * 64;
    }
    if (bk >= 0) pos = atomicAdd(&h[bk], 1);
    __syncthreads();
    if (tid < 12 && h[tid] > 0) {
        basev[tid] = (tid < 9) ? atomicAdd(&g_ecnt[tid], h[tid])
                               : atomicAdd(&g_ncnt[tid-9], h[tid]);
    }
    __syncthreads();
    if (bk >= 0) {
        int base = basev[bk];
        if (bk < 9) {
            g_ebucket[bk*NETASK + base + pos] = val;
            g_eoff   [bk*NETASK + base + pos] = off;
        } else {
            g_nbucket[(bk-9)*NNODE + base + pos] = val;
            g_noff   [(bk-9)*NNODE + base + pos] = off;
        }
    }
}

// ---------------- 32x64 @ 64x64 layer, 256 thr, 2 rows x 4 cols/thread ----
static __device__ __forceinline__ void layer64(const float* __restrict__ sIn,
                                               const float* __restrict__ sW,
                                               const float* __restrict__ sb,
                                               int r0, int colb, u64 acc[4]) {
    ulonglong2 bv = *(const ulonglong2*)(sb + colb);
    acc[0] = bv.x; acc[1] = bv.y; acc[2] = bv.x; acc[3] = bv.y;
    const float* in0 = sIn + r0*68;
    const float* in1 = sIn + (r0+4)*68;
    #pragma unroll
    for (int d0 = 0; d0 < 64; d0 += 4) {
        float4 x0 = *(const float4*)(in0 + d0);
        float4 x1 = *(const float4*)(in1 + d0);
        {
            ulonglong2 w = *(const ulonglong2*)(sW + (d0+0)*64 + colb);
            u64 a0 = pack2(x0.x, x0.x), a1 = pack2(x1.x, x1.x);
            ffma2(acc[0], a0, w.x); ffma2(acc[1], a0, w.y);
            ffma2(acc[2], a1, w.x); ffma2(acc[3], a1, w.y);
        }
        {
            ulonglong2 w = *(const ulonglong2*)(sW + (d0+1)*64 + colb);
            u64 a0 = pack2(x0.y, x0.y), a1 = pack2(x1.y, x1.y);
            ffma2(acc[0], a0, w.x); ffma2(acc[1], a0, w.y);
            ffma2(acc[2], a1, w.x); ffma2(acc[3], a1, w.y);
        }
        {
            ulonglong2 w = *(const ulonglong2*)(sW + (d0+2)*64 + colb);
            u64 a0 = pack2(x0.z, x0.z), a1 = pack2(x1.z, x1.z);
            ffma2(acc[0], a0, w.x); ffma2(acc[1], a0, w.y);
            ffma2(acc[2], a1, w.x); ffma2(acc[3], a1, w.y);
        }
        {
            ulonglong2 w = *(const ulonglong2*)(sW + (d0+3)*64 + colb);
            u64 a0 = pack2(x0.w, x0.w), a1 = pack2(x1.w, x1.w);
            ffma2(acc[0], a0, w.x); ffma2(acc[1], a0, w.y);
            ffma2(acc[2], a1, w.x); ffma2(acc[3], a1, w.y);
        }
    }
}

static __device__ __forceinline__ void store_relu(float* __restrict__ sOut,
                                                  int r0, int colb, const u64 acc[4]) {
    float a, b, c, d;
    unpack2(acc[0], a, b); unpack2(acc[1], c, d);
    *(float4*)(sOut + r0*68 + colb) =
        make_float4(fmaxf(a,0.f), fmaxf(b,0.f), fmaxf(c,0.f), fmaxf(d,0.f));
    unpack2(acc[2], a, b); unpack2(acc[3], c, d);
    *(float4*)(sOut + (r0+4)*68 + colb) =
        make_float4(fmaxf(a,0.f), fmaxf(b,0.f), fmaxf(c,0.f), fmaxf(d,0.f));
}

// ---------------- MLP: prefix-scan role map + one-front staging, 3 syncs ---
__global__ __launch_bounds__(256) void mlp_kernel(
    const float* __restrict__ node_enc, const float* __restrict__ edge_enc,
    const float* __restrict__ nW0, const float* __restrict__ nb0,
    const float* __restrict__ nW1, const float* __restrict__ nb1,
    const float* __restrict__ nW2, const float* __restrict__ nb2,
    const float* __restrict__ eW0, const float* __restrict__ eb0,
    const float* __restrict__ eW1, const float* __restrict__ eb1,
    const float* __restrict__ eW2, const float* __restrict__ eb2)
{
    extern __shared__ __align__(16) float dsm[];
    float* sW0 = dsm;                 // 4096
    float* sW1 = dsm + 4096;          // 4096
    float* sW2 = dsm + 8192;          // 4096
    float* sA  = dsm + 12288;         // 32*68
    float* sB  = dsm + 14464;         // 32*68
    float* sb0 = dsm + 16640;
    float* sb1 = dsm + 16704;
    float* sb2 = dsm + 16768;

    int tid = threadIdx.x, bid = blockIdx.x;

    // ---- prefix-scan role map: zero dead CTAs ----
    int g = -1, chunk = 0, acc = 0, cnt = 0;
    bool isEdge = true;
    #pragma unroll
    for (int t = 0; t < NET; t++) {
        int n = __ldcg(&g_ecnt[t]);
        int c = (n + 31) >> 5;
        if (g < 0 && bid < acc + c) { g = t; chunk = bid - acc; cnt = n; }
        acc += c;
    }
    if (g < 0) {
        isEdge = false;
        int nb = bid - acc; acc = 0;
        #pragma unroll
        for (int t = 0; t < NT; t++) {
            int n = __ldcg(&g_ncnt[t]);
            int c = (n + 31) >> 5;
            if (g < 0 && nb < acc + c) { g = t; chunk = nb - acc; cnt = n; }
            acc += c;
        }
        if (g < 0) return;
    }
    int base  = chunk * 32;
    int ntask = min(32, cnt - base);

    // ---- critical-chain loads first: offsets + output indices ----
    int s = tid >> 4, q = tid & 15;
    int sc = base + min(s, ntask - 1);           // clamped (partial chunks)
    int sc16 = base + min(s + 16, ntask - 1);
    int warp = tid >> 5, lane = tid & 31;
    int colb = (warp & 1) * 32 + (lane & 7) * 4;
    int r0   = (warp >> 1) * 8 + (lane >> 3);
    int offA, offB, idx0 = 0, idx1 = 0;
    const float* inBase;
    if (isEdge) {
        offA = __ldcg(&g_eoff[g*NETASK + sc]);
        offB = __ldcg(&g_eoff[g*NETASK + sc16]);
        idx0 = __ldcg(&g_ebucket[g*NETASK + base + min(r0, ntask-1)]);
        idx1 = __ldcg(&g_ebucket[g*NETASK + base + min(r0+4, ntask-1)]);
        inBase = edge_enc;
    } else {
        offA = __ldcg(&g_noff[g*NNODE + sc]);
        offB = __ldcg(&g_noff[g*NNODE + sc16]);
        idx0 = __ldcg(&g_nbucket[g*NNODE + base + min(tid >> 3, ntask-1)]);
        inBase = node_enc;
    }

    // ---- independent loads behind them: all weights + biases ----
    const float *W0, *W1, *b0, *b1;
    if (isEdge) {
        W0 = eW0 + g*4096; W1 = eW1 + g*4096;
        b0 = eb0 + g*64;   b1 = eb1 + g*64;
    } else {
        W0 = nW0 + g*4096; W1 = nW1 + g*4096;
        b0 = nb0 + g*64;   b1 = nb1 + g*64;
    }
    {
        const float4* w0 = (const float4*)W0;
        const float4* w1 = (const float4*)W1;
        float4* s0 = (float4*)sW0; float4* s1 = (float4*)sW1;
        #pragma unroll
        for (int k = 0; k < 4; k++) {
            s0[tid + 256*k] = w0[tid + 256*k];
            s1[tid + 256*k] = w1[tid + 256*k];
        }
    }
    if (isEdge) {
        const float4* w2 = (const float4*)(eW2 + g*4096);
        float4* s2 = (float4*)sW2;
        #pragma unroll
        for (int k = 0; k < 4; k++) s2[tid + 256*k] = w2[tid + 256*k];
    } else if (tid < 128) {
        ((float4*)sW2)[tid] = ((const float4*)(nW2 + g*512))[tid];
    }
    if (tid < 64) {
        sb0[tid] = b0[tid];
        sb1[tid] = b1[tid];
        sb2[tid] = isEdge ? eb2[g*64 + tid] : (tid < 8 ? nb2[g*8 + tid] : 0.f);
    }

    // ---- gather (depends only on offsets) ----
    *(float4*)(sA + s*68 + q*4)      = *(const float4*)(inBase + (size_t)offA + q*4);
    *(float4*)(sA + (s+16)*68 + q*4) = *(const float4*)(inBase + (size_t)offB + q*4);
    __syncthreads();                                         // sync 1

    u64 a4[4];
    layer64(sA, sW0, sb0, r0, colb, a4);                     // layer 0
    store_relu(sB, r0, colb, a4);
    __syncthreads();                                         // sync 2

    layer64(sB, sW1, sb1, r0, colb, a4);                     // layer 1
    store_relu(sA, r0, colb, a4);
    __syncthreads();                                         // sync 3

    if (isEdge) {                                            // layer 2 (edge)
        layer64(sA, sW2, sb2, r0, colb, a4);
        float a, b, c, d;
        if (r0 < ntask) {
            unpack2(a4[0], a, b); unpack2(a4[1], c, d);
            *(float4*)(g_ef + (size_t)idx0*64 + colb) = make_float4(a, b, c, d);
        }
        if (r0 + 4 < ntask) {
            unpack2(a4[2], a, b); unpack2(a4[3], c, d);
            *(float4*)(g_ef + (size_t)idx1*64 + colb) = make_float4(a, b, c, d);
        }
    } else {                                                 // layer 2 (node)
        int row = tid >> 3, col = tid & 7;
        float a = sb2[col];
        const float* in = sA + row*68;
        #pragma unroll 16
        for (int d = 0; d < 64; d++) a += in[d] * sW2[d*8 + col];
        if (row < ntask) g_nf[(size_t)idx0*8 + col] = a;
    }
    __threadfence();
    cudaTriggerProgrammaticLaunchCompletion();
}

// ---------------- kernel: assemble logpi (PDL; z-tail pre-sync) ----------
__global__ __launch_bounds__(256) void assemble_kernel(
    const int* __restrict__ cni, float* __restrict__ out, int writeZ)
{
    int tid = threadIdx.x;
    int sub = tid >> 6;
    int t   = tid & 63;
    int cq  = blockIdx.x * 4 + sub;

    __shared__ float e[4][192];
    __shared__ float nf[4][3][8];

    if (blockIdx.x == 0 && writeZ) {
        for (int m = tid; m < 512; m += 256) {
            int i = m >> 6, j = (m >> 3) & 7, k = m & 7;
            float* p = out + OUT_LOGPI + (size_t)m*3;
            p[0] = (float)i; p[1] = (float)j; p[2] = (float)k;
        }
    }

    cudaGridDependencySynchronize();

    if (blockIdx.x == 0) {               // reset counters for next replay
        if (tid < NET) g_ecnt[tid] = 0;
        if (tid < NT)  g_ncnt[tid] = 0;
    }

    size_t tbase = (size_t)cq * 192;
    e[sub][t]       = __ldcg(&g_ef[tbase + t]);
    e[sub][t + 64]  = __ldcg(&g_ef[tbase + t + 64]);
    e[sub][t + 128] = __ldcg(&g_ef[tbase + t + 128]);
    if (t < 24) {
        int k = t >> 3, zz = t & 7;
        int b = cq / NC;
        int node = clampi(cni[cq*3 + k], 0, NA-1);
        nf[sub][k][zz] = __ldcg(&g_nf[((size_t)b*NA + node)*8 + zz]);
    }
    __syncthreads();

    int z0 = t >> 3, z1 = t & 7;
    float bse = nf[sub][0][z0] + nf[sub][1][z1] + e[sub][z0*8 + z1];
    float r[8];
    #pragma unroll
    for (int z2 = 0; z2 < 8; z2++)
        r[z2] = bse + nf[sub][2][z2] + e[sub][64 + z0*8 + z2] + e[sub][128 + z1*8 + z2];
    float* op = out + (size_t)cq*512 + t*8;
    *(float4*)op       = make_float4(r[0], r[1], r[2], r[3]);
    *(float4*)(op + 4) = make_float4(r[4], r[5], r[6], r[7]);
}

// ---------------- launch ----------------
extern "C" void kernel_launch(void* const* d_in, const int* in_sizes, int n_in,
                              void* d_out, int out_size) {
    const int*   types    = (const int*)d_in[0];
    const float* node_enc = (const float*)d_in[1];
    const float* edge_enc = (const float*)d_in[2];
    const int*   cni      = (const int*)d_in[4];
    const float* nW0 = (const float*)d_in[6];
    const float* nb0 = (const float*)d_in[7];
    const float* nW1 = (const float*)d_in[8];
    const float* nb1 = (const float*)d_in[9];
    const float* nW2 = (const float*)d_in[10];
    const float* nb2 = (const float*)d_in[11];
    const float* eW0 = (const float*)d_in[12];
    const float* eb0 = (const float*)d_in[13];
    const float* eW1 = (const float*)d_in[14];
    const float* eb1 = (const float*)d_in[15];
    const float* eW2 = (const float*)d_in[16];
    const float* eb2 = (const float*)d_in[17];
    float* out = (float*)d_out;

    int writeZ = (out_size >= OUT_LOGPI + 512*3) ? 1 : 0;

    cudaFuncSetAttribute(mlp_kernel,
                         cudaFuncAttributeMaxDynamicSharedMemorySize, MLP_SMEM);

    bin_tasks_kernel<<<28, 256>>>(types, cni);
    mlp_kernel<<<240, 256, MLP_SMEM>>>(node_enc, edge_enc,
                                       nW0, nb0, nW1, nb1, nW2, nb2,
                                       eW0, eb0, eW1, eb1, eW2, eb2);

    // PDL only on mlp->assemble (pre-sync work is tiny)
    cudaLaunchAttribute attr[1];
    attr[0].id = cudaLaunchAttributeProgrammaticStreamSerialization;
    attr[0].val.programmaticStreamSerializationAllowed = 1;
    cudaLaunchConfig_t cfg = {};
    cfg.gridDim  = dim3(BS * NC / 4, 1, 1);
    cfg.blockDim = dim3(256, 1, 1);
    cfg.stream   = 0;
    cfg.attrs    = attr;
    cfg.numAttrs = 1;
    cudaLaunchKernelEx(&cfg, assemble_kernel, cni, out, writeZ);
}

// round 13
// speedup vs baseline: 1.0681x; 1.0097x over previous
#include <cuda_runtime.h>

// Problem constants (fixed by setup_inputs)
#define BS   8
#define NA   128
#define NC   256
#define ZZ   8
#define NT   3
#define NET  9
#define NCLQ (BS*NC)       // 2048 cliques
#define NETASK (NCLQ*3)    // 6144 edge tasks
#define NNODE  (BS*NA)     // 1024 node tasks
#define OUT_LOGPI (BS*NC*ZZ*ZZ*ZZ)   // 1048576
#define ECH 32             // chunks per edge type (capacity 1024)
#define NCH 16             // chunks per node type (capacity 512)
#define MLP_GRID (NET*ECH + NT*NCH)  // 336
#define MLP_SMEM 65536

typedef unsigned long long u64;

// ---------------- device scratch (no allocations allowed) ----------------
__device__ __align__(16) float g_nf[NNODE*ZZ];
__device__ __align__(16) float g_ef[NETASK*64];

static __device__ __forceinline__ int clampi(int v, int lo, int hi) {
    return v < lo ? lo : (v > hi ? hi : v);
}

// ---------------- packed f32x2 helpers (FFMA2) ----------------
static __device__ __forceinline__ u64 pack2(float a, float b) {
    u64 r; asm("mov.b64 %0, {%1, %2};" : "=l"(r) : "f"(a), "f"(b)); return r;
}
static __device__ __forceinline__ void unpack2(u64 v, float& a, float& b) {
    asm("mov.b64 {%0, %1}, %2;" : "=f"(a), "=f"(b) : "l"(v));
}
static __device__ __forceinline__ void ffma2(u64& d, u64 a, u64 b) {
    asm("fma.rn.f32x2 %0, %1, %2, %0;" : "+l"(d) : "l"(a), "l"(b));
}

// ---------------- 32x64 @ 64x64 layer, 256 thr, 2 rows x 4 cols/thread ----
static __device__ __forceinline__ void layer64(const float* __restrict__ sIn,
                                               const float* __restrict__ sW,
                                               const float* __restrict__ sb,
                                               int r0, int colb, u64 acc[4]) {
    ulonglong2 bv = *(const ulonglong2*)(sb + colb);
    acc[0] = bv.x; acc[1] = bv.y; acc[2] = bv.x; acc[3] = bv.y;
    const float* in0 = sIn + r0*68;
    const float* in1 = sIn + (r0+4)*68;
    #pragma unroll
    for (int d0 = 0; d0 < 64; d0 += 4) {
        float4 x0 = *(const float4*)(in0 + d0);
        float4 x1 = *(const float4*)(in1 + d0);
        {
            ulonglong2 w = *(const ulonglong2*)(sW + (d0+0)*64 + colb);
            u64 a0 = pack2(x0.x, x0.x), a1 = pack2(x1.x, x1.x);
            ffma2(acc[0], a0, w.x); ffma2(acc[1], a0, w.y);
            ffma2(acc[2], a1, w.x); ffma2(acc[3], a1, w.y);
        }
        {
            ulonglong2 w = *(const ulonglong2*)(sW + (d0+1)*64 + colb);
            u64 a0 = pack2(x0.y, x0.y), a1 = pack2(x1.y, x1.y);
            ffma2(acc[0], a0, w.x); ffma2(acc[1], a0, w.y);
            ffma2(acc[2], a1, w.x); ffma2(acc[3], a1, w.y);
        }
        {
            ulonglong2 w = *(const ulonglong2*)(sW + (d0+2)*64 + colb);
            u64 a0 = pack2(x0.z, x0.z), a1 = pack2(x1.z, x1.z);
            ffma2(acc[0], a0, w.x); ffma2(acc[1], a0, w.y);
            ffma2(acc[2], a1, w.x); ffma2(acc[3], a1, w.y);
        }
        {
            ulonglong2 w = *(const ulonglong2*)(sW + (d0+3)*64 + colb);
            u64 a0 = pack2(x0.w, x0.w), a1 = pack2(x1.w, x1.w);
            ffma2(acc[0], a0, w.x); ffma2(acc[1], a0, w.y);
            ffma2(acc[2], a1, w.x); ffma2(acc[3], a1, w.y);
        }
    }
}

static __device__ __forceinline__ void store_relu(float* __restrict__ sOut,
                                                  int r0, int colb, const u64 acc[4]) {
    float a, b, c, d;
    unpack2(acc[0], a, b); unpack2(acc[1], c, d);
    *(float4*)(sOut + r0*68 + colb) =
        make_float4(fmaxf(a,0.f), fmaxf(b,0.f), fmaxf(c,0.f), fmaxf(d,0.f));
    unpack2(acc[2], a, b); unpack2(acc[3], c, d);
    *(float4*)(sOut + (r0+4)*68 + colb) =
        make_float4(fmaxf(a,0.f), fmaxf(b,0.f), fmaxf(c,0.f), fmaxf(d,0.f));
}

// ---------------- MLP with in-CTA redundant binning (no bin kernel) --------
__global__ __launch_bounds__(256) void mlp_kernel(
    const int* __restrict__ types, const int* __restrict__ cni,
    const float* __restrict__ node_enc, const float* __restrict__ edge_enc,
    const float* __restrict__ nW0, const float* __restrict__ nb0,
    const float* __restrict__ nW1, const float* __restrict__ nb1,
    const float* __restrict__ nW2, const float* __restrict__ nb2,
    const float* __restrict__ eW0, const float* __restrict__ eb0,
    const float* __restrict__ eW1, const float* __restrict__ eb1,
    const float* __restrict__ eW2, const float* __restrict__ eb2)
{
    extern __shared__ __align__(16) float dsm[];
    float* sW   = dsm;                    // 4096 floats
    float* sA   = dsm + 4096;             // 2176
    float* sB   = dsm + 6272;             // 2176
    float* sb0  = dsm + 8448;             // 64
    float* sb1  = dsm + 8512;             // 64
    float* sb2  = dsm + 8576;             // 64
    int*   sT   = (int*)(dsm + 8640);     // 1024
    int*   sCNI = (int*)(dsm + 9664);     // 6144
    int*   sWS  = (int*)(dsm + 15808);    // 8  (warp sums)
    int*   sSelI= (int*)(dsm + 15816);    // 32 (selected task ids)
    int*   sSelO= (int*)(dsm + 15848);    // 32 (selected offsets)

    int tid = threadIdx.x, bid = blockIdx.x;
    int warp = tid >> 5, lane = tid & 31;

    // static role map
    bool isEdge = bid < NET*ECH;
    int g, base;
    if (isEdge) { g = bid >> 5; base = (bid & 31) * 32; }
    else { int nb = bid - NET*ECH; g = nb >> 4; base = (nb & 15) * 32; }

    const float *W0, *W1, *b0, *b1, *inBase;
    if (isEdge) {
        W0 = eW0 + g*4096; W1 = eW1 + g*4096;
        b0 = eb0 + g*64;   b1 = eb1 + g*64;
        inBase = edge_enc;
    } else {
        W0 = nW0 + g*4096; W1 = nW1 + g*4096;
        b0 = nb0 + g*64;   b1 = nb1 + g*64;
        inBase = node_enc;
    }

    // ---- step 1: issue weight loads (independent), stage types/cni -------
    {
        const float4* w = (const float4*)W0;
        float4* sw = (float4*)sW;
        #pragma unroll
        for (int k = 0; k < 4; k++) sw[tid + 256*k] = w[tid + 256*k];
        if (tid < 64) { sb0[tid] = b0[tid]; sb1[tid] = b1[tid]; }
    }
    float4 pw[4];
    {
        const float4* w = (const float4*)W1;
        #pragma unroll
        for (int k = 0; k < 4; k++) pw[k] = w[tid + 256*k];
    }
    if (isEdge) { if (tid < 64) sb2[tid] = eb2[g*64 + tid]; }
    else        { if (tid < 8)  sb2[tid] = nb2[g*8 + tid]; }

    ((int4*)sT)[tid] = ((const int4*)types)[tid];           // 4KB types
    if (isEdge) {
        #pragma unroll
        for (int k = 0; k < 6; k++)                         // 24KB cni
            ((int4*)sCNI)[tid + 256*k] = ((const int4*)cni)[tid + 256*k];
    }
    if (tid < 32) { sSelI[tid] = 0; sSelO[tid] = 0; }
    __syncthreads();                                        // sync A

    // ---- step 2: pass 1 — classify this thread's contiguous task slice ---
    int c_local = 0;
    unsigned ep0 = 0, ep1 = 0, ep2 = 0;   // 4-bit packed pair types per clique
    if (isEdge) {
        int cq0 = tid * 8;
        #pragma unroll
        for (int qq = 0; qq < 8; qq++) {
            int cq = cq0 + qq;
            int b  = cq >> 8;
            int i0 = clampi(sCNI[cq*3+0], 0, NA-1);
            int i1 = clampi(sCNI[cq*3+1], 0, NA-1);
            int i2 = clampi(sCNI[cq*3+2], 0, NA-1);
            int t0 = clampi(sT[b*NA+i0], 0, NT-1);
            int t1 = clampi(sT[b*NA+i1], 0, NT-1);
            int t2 = clampi(sT[b*NA+i2], 0, NT-1);
            unsigned e0 = t1*3 + t0;      // pair (0,1): i=i0, j=i1
            unsigned e1 = t2*3 + t0;      // pair (0,2)
            unsigned e2 = t2*3 + t1;      // pair (1,2)
            ep0 |= e0 << (qq*4); ep1 |= e1 << (qq*4); ep2 |= e2 << (qq*4);
            c_local += (e0 == (unsigned)g) + (e1 == (unsigned)g) + (e2 == (unsigned)g);
        }
    } else {
        int nn0 = tid * 4;
        #pragma unroll
        for (int k = 0; k < 4; k++) {
            unsigned ty = clampi(sT[nn0 + k], 0, NT-1);
            ep0 |= ty << (k*4);
            c_local += (ty == (unsigned)g);
        }
    }

    // ---- step 3: 256-wide exclusive scan of c_local -----------------------
    int x = c_local;
    #pragma unroll
    for (int d = 1; d < 32; d <<= 1) {
        int y = __shfl_up_sync(0xffffffffu, x, d);
        if (lane >= d) x += y;
    }
    if (lane == 31) sWS[warp] = x;
    __syncthreads();                                        // sync B
    int wbase = 0, cnt = 0;
    #pragma unroll
    for (int w = 0; w < 8; w++) {
        int v = sWS[w];
        if (w < warp) wbase += v;
        cnt += v;
    }
    int excl = wbase + x - c_local;

    if (base >= cnt) return;              // empty chunk: uniform exit
    int ntask = min(32, cnt - base);

    // ---- step 4: pass 2 — emit (idx, offset) for tasks in our window -----
    if (excl < base + 32 && excl + c_local > base) {
        int r = excl;
        if (isEdge) {
            int cq0 = tid * 8;
            #pragma unroll
            for (int qq = 0; qq < 8; qq++) {
                int cq = cq0 + qq;
                unsigned e0 = (ep0 >> (qq*4)) & 15u;
                unsigned e1 = (ep1 >> (qq*4)) & 15u;
                unsigned e2 = (ep2 >> (qq*4)) & 15u;
                #pragma unroll
                for (int p = 0; p < 3; p++) {
                    unsigned e = (p == 0) ? e0 : (p == 1) ? e1 : e2;
                    if (e == (unsigned)g) {
                        if (r >= base && r < base + 32) {
                            int a0 = (p == 2) ? 1 : 0;
                            int a1 = (p == 0) ? 1 : 2;
                            int i = clampi(sCNI[cq*3 + a0], 0, NA-1);
                            int j = clampi(sCNI[cq*3 + a1], 0, NA-1);
                            int b = cq >> 8;
                            sSelI[r - base] = cq*3 + p;
                            sSelO[r - base] = ((b*NA + i)*NA + j) * 64;
                        }
                        r++;
                    }
                }
            }
        } else {
            int nn0 = tid * 4;
            #pragma unroll
            for (int k = 0; k < 4; k++) {
                unsigned ty = (ep0 >> (k*4)) & 15u;
                if (ty == (unsigned)g) {
                    if (r >= base && r < base + 32) {
                        sSelI[r - base] = nn0 + k;
                        sSelO[r - base] = (nn0 + k) * 64;
                    }
                    r++;
                }
            }
        }
    }
    __syncthreads();                                        // sync C

    // ---- step 5: gather inputs -------------------------------------------
    int s = tid >> 4, q = tid & 15;
    *(float4*)(sA + s*68 + q*4)      = *(const float4*)(inBase + (size_t)sSelO[s]    + q*4);
    *(float4*)(sA + (s+16)*68 + q*4) = *(const float4*)(inBase + (size_t)sSelO[s+16] + q*4);
    __syncthreads();                                        // sync D

    int colb = (warp & 1) * 32 + (lane & 7) * 4;
    int r0   = (warp >> 1) * 8 + (lane >> 3);

    u64 a4[4];
    layer64(sA, sW, sb0, r0, colb, a4);                     // layer 0
    __syncthreads();
    store_relu(sB, r0, colb, a4);
    {   // W1 regs -> smem; prefetch W2
        float4* sw = (float4*)sW;
        #pragma unroll
        for (int k = 0; k < 4; k++) sw[tid + 256*k] = pw[k];
    }
    if (isEdge) {
        const float4* w = (const float4*)(eW2 + g*4096);
        #pragma unroll
        for (int k = 0; k < 4; k++) pw[k] = w[tid + 256*k];
    } else {
        if (tid < 128) pw[0] = ((const float4*)(nW2 + g*512))[tid];
    }
    __syncthreads();

    layer64(sB, sW, sb1, r0, colb, a4);                     // layer 1
    __syncthreads();
    store_relu(sA, r0, colb, a4);
    {   // W2 regs -> smem
        float4* sw = (float4*)sW;
        if (isEdge) {
            #pragma unroll
            for (int k = 0; k < 4; k++) sw[tid + 256*k] = pw[k];
        } else {
            if (tid < 128) sw[tid] = pw[0];
        }
    }
    __syncthreads();

    if (isEdge) {                                           // layer 2 (edge)
        layer64(sA, sW, sb2, r0, colb, a4);
        float a, b, c, d;
        if (r0 < ntask) {
            unpack2(a4[0], a, b); unpack2(a4[1], c, d);
            *(float4*)(g_ef + (size_t)sSelI[r0]*64 + colb) = make_float4(a, b, c, d);
        }
        if (r0 + 4 < ntask) {
            unpack2(a4[2], a, b); unpack2(a4[3], c, d);
            *(float4*)(g_ef + (size_t)sSelI[r0+4]*64 + colb) = make_float4(a, b, c, d);
        }
    } else {                                                // layer 2 (node)
        int row = tid >> 3, col = tid & 7;
        float a = sb2[col];
        const float* in = sA + row*68;
        #pragma unroll 16
        for (int d = 0; d < 64; d++) a += in[d] * sW[d*8 + col];
        if (row < ntask) g_nf[(size_t)sSelI[row]*8 + col] = a;
    }
    __threadfence();
    cudaTriggerProgrammaticLaunchCompletion();
}

// ---------------- kernel: assemble logpi (PDL; z-tail pre-sync) ----------
__global__ __launch_bounds__(256) void assemble_kernel(
    const int* __restrict__ cni, float* __restrict__ out, int writeZ)
{
    int tid = threadIdx.x;
    int sub = tid >> 6;
    int t   = tid & 63;
    int cq  = blockIdx.x * 4 + sub;

    __shared__ float e[4][192];
    __shared__ float nf[4][3][8];

    if (blockIdx.x == 0 && writeZ) {
        for (int m = tid; m < 512; m += 256) {
            int i = m >> 6, j = (m >> 3) & 7, k = m & 7;
            float* p = out + OUT_LOGPI + (size_t)m*3;
            p[0] = (float)i; p[1] = (float)j; p[2] = (float)k;
        }
    }

    cudaGridDependencySynchronize();

    size_t tbase = (size_t)cq * 192;
    e[sub][t]       = __ldcg(&g_ef[tbase + t]);
    e[sub][t + 64]  = __ldcg(&g_ef[tbase + t + 64]);
    e[sub][t + 128] = __ldcg(&g_ef[tbase + t + 128]);
    if (t < 24) {
        int k = t >> 3, zz = t & 7;
        int b = cq / NC;
        int node = clampi(cni[cq*3 + k], 0, NA-1);
        nf[sub][k][zz] = __ldcg(&g_nf[((size_t)b*NA + node)*8 + zz]);
    }
    __syncthreads();

    int z0 = t >> 3, z1 = t & 7;
    float bse = nf[sub][0][z0] + nf[sub][1][z1] + e[sub][z0*8 + z1];
    float r[8];
    #pragma unroll
    for (int z2 = 0; z2 < 8; z2++)
        r[z2] = bse + nf[sub][2][z2] + e[sub][64 + z0*8 + z2] + e[sub][128 + z1*8 + z2];
    float* op = out + (size_t)cq*512 + t*8;
    *(float4*)op       = make_float4(r[0], r[1], r[2], r[3]);
    *(float4*)(op + 4) = make_float4(r[4], r[5], r[6], r[7]);
}

// ---------------- launch ----------------
extern "C" void kernel_launch(void* const* d_in, const int* in_sizes, int n_in,
                              void* d_out, int out_size) {
    const int*   types    = (const int*)d_in[0];
    const float* node_enc = (const float*)d_in[1];
    const float* edge_enc = (const float*)d_in[2];
    const int*   cni      = (const int*)d_in[4];
    const float* nW0 = (const float*)d_in[6];
    const float* nb0 = (const float*)d_in[7];
    const float* nW1 = (const float*)d_in[8];
    const float* nb1 = (const float*)d_in[9];
    const float* nW2 = (const float*)d_in[10];
    const float* nb2 = (const float*)d_in[11];
    const float* eW0 = (const float*)d_in[12];
    const float* eb0 = (const float*)d_in[13];
    const float* eW1 = (const float*)d_in[14];
    const float* eb1 = (const float*)d_in[15];
    const float* eW2 = (const float*)d_in[16];
    const float* eb2 = (const float*)d_in[17];
    float* out = (float*)d_out;

    int writeZ = (out_size >= OUT_LOGPI + 512*3) ? 1 : 0;

    cudaFuncSetAttribute(mlp_kernel,
                         cudaFuncAttributeMaxDynamicSharedMemorySize, MLP_SMEM);

    mlp_kernel<<<MLP_GRID, 256, MLP_SMEM>>>(types, cni, node_enc, edge_enc,
                                            nW0, nb0, nW1, nb1, nW2, nb2,
                                            eW0, eb0, eW1, eb1, eW2, eb2);

    // PDL on mlp->assemble (pre-sync work is tiny)
    cudaLaunchAttribute attr[1];
    attr[0].id = cudaLaunchAttributeProgrammaticStreamSerialization;
    attr[0].val.programmaticStreamSerializationAllowed = 1;
    cudaLaunchConfig_t cfg = {};
    cfg.gridDim  = dim3(BS * NC / 4, 1, 1);
    cfg.blockDim = dim3(256, 1, 1);
    cfg.stream   = 0;
    cfg.attrs    = attr;
    cfg.numAttrs = 1;
    cudaLaunchKernelEx(&cfg, assemble_kernel, cni, out, writeZ);
}

// round 14
// speedup vs baseline: 1.1652x; 1.0909x over previous
#include <cuda_runtime.h>

// Problem constants (fixed by setup_inputs)
#define BS   8
#define NA   128
#define NC   256
#define ZZ   8
#define NT   3
#define NET  9
#define NETASK (BS*NC*3)   // 6144 edge tasks
#define NNODE  (BS*NA)     // 1024 node tasks
#define NTASKS (NETASK + NNODE)  // 7168
#define OUT_LOGPI (BS*NC*ZZ*ZZ*ZZ)   // 1048576

typedef unsigned long long u64;

// ---------------- device scratch (no allocations allowed) ----------------
__device__ __align__(16) float g_nf[NNODE*ZZ];
__device__ __align__(16) float g_ef[NETASK*64];
__device__ int g_ecnt[NET];          // zero at load; re-zeroed by assemble
__device__ int g_ncnt[NT];
__device__ int g_ebucket[NET*NETASK];
__device__ int g_nbucket[NT*NNODE];

static __device__ __forceinline__ int clampi(int v, int lo, int hi) {
    return v < lo ? lo : (v > hi ? hi : v);
}

// ---------------- packed f32x2 helpers (FFMA2) ----------------
static __device__ __forceinline__ u64 pack2(float a, float b) {
    u64 r; asm("mov.b64 %0, {%1, %2};" : "=l"(r) : "f"(a), "f"(b)); return r;
}
static __device__ __forceinline__ void unpack2(u64 v, float& a, float& b) {
    asm("mov.b64 {%0, %1}, %2;" : "=f"(a), "=f"(b) : "l"(v));
}
static __device__ __forceinline__ void ffma2(u64& d, u64 a, u64 b) {
    asm("fma.rn.f32x2 %0, %1, %2, %0;" : "+l"(d) : "l"(a), "l"(b));
}

// ---------------- kernel: bin tasks (R3 champion version) ------------------
__global__ void bin_tasks_kernel(const int* __restrict__ types,
                                 const int* __restrict__ cni) {
    __shared__ int h[12];
    __shared__ int basev[12];
    int tid = threadIdx.x;
    int t = blockIdx.x * 256 + tid;
    if (tid < 12) h[tid] = 0;
    __syncthreads();

    int bk = -1, val = 0, pos = 0;
    if (t < NETASK) {
        int b   = t / (NC*3);
        int rem = t - b*(NC*3);
        int c   = rem / 3;
        int p   = rem - 3*c;              // pair: 0->(0,1) 1->(0,2) 2->(1,2)
        int a0  = (p == 2) ? 1 : 0;
        int a1  = (p == 0) ? 1 : 2;
        int i = clampi(cni[(b*NC + c)*3 + a0], 0, NA-1);
        int j = clampi(cni[(b*NC + c)*3 + a1], 0, NA-1);
        int ti = clampi(types[b*NA + i], 0, NT-1);
        int tj = clampi(types[b*NA + j], 0, NT-1);
        bk = tj*3 + ti;                   // emask: pa==type[j], pb==type[i]
        val = t;
    } else if (t < NTASKS) {
        int nn = t - NETASK;
        bk = 9 + clampi(types[nn], 0, NT-1);
        val = nn;
    }
    if (bk >= 0) pos = atomicAdd(&h[bk], 1);
    __syncthreads();
    if (tid < 12 && h[tid] > 0) {
        basev[tid] = (tid < 9) ? atomicAdd(&g_ecnt[tid], h[tid])
                               : atomicAdd(&g_ncnt[tid-9], h[tid]);
    }
    __syncthreads();
    if (bk >= 0) {
        int base = basev[bk];
        if (bk < 9) g_ebucket[bk*NETASK + base + pos] = val;
        else        g_nbucket[(bk-9)*NNODE + base + pos] = val;
    }
}

// ---------------- 32x64 @ 64x64 layer, 256 thr, 2 rows x 4 cols/thread ----
static __device__ __forceinline__ void layer64(const float* __restrict__ sIn,
                                               const float* __restrict__ sW,
                                               const float* __restrict__ sb,
                                               int r0, int colb, u64 acc[4]) {
    ulonglong2 bv = *(const ulonglong2*)(sb + colb);
    acc[0] = bv.x; acc[1] = bv.y; acc[2] = bv.x; acc[3] = bv.y;
    const float* in0 = sIn + r0*68;
    const float* in1 = sIn + (r0+4)*68;
    #pragma unroll
    for (int d0 = 0; d0 < 64; d0 += 4) {
        float4 x0 = *(const float4*)(in0 + d0);
        float4 x1 = *(const float4*)(in1 + d0);
        {
            ulonglong2 w = *(const ulonglong2*)(sW + (d0+0)*64 + colb);
            u64 a0 = pack2(x0.x, x0.x), a1 = pack2(x1.x, x1.x);
            ffma2(acc[0], a0, w.x); ffma2(acc[1], a0, w.y);
            ffma2(acc[2], a1, w.x); ffma2(acc[3], a1, w.y);
        }
        {
            ulonglong2 w = *(const ulonglong2*)(sW + (d0+1)*64 + colb);
            u64 a0 = pack2(x0.y, x0.y), a1 = pack2(x1.y, x1.y);
            ffma2(acc[0], a0, w.x); ffma2(acc[1], a0, w.y);
            ffma2(acc[2], a1, w.x); ffma2(acc[3], a1, w.y);
        }
        {
            ulonglong2 w = *(const ulonglong2*)(sW + (d0+2)*64 + colb);
            u64 a0 = pack2(x0.z, x0.z), a1 = pack2(x1.z, x1.z);
            ffma2(acc[0], a0, w.x); ffma2(acc[1], a0, w.y);
            ffma2(acc[2], a1, w.x); ffma2(acc[3], a1, w.y);
        }
        {
            ulonglong2 w = *(const ulonglong2*)(sW + (d0+3)*64 + colb);
            u64 a0 = pack2(x0.w, x0.w), a1 = pack2(x1.w, x1.w);
            ffma2(acc[0], a0, w.x); ffma2(acc[1], a0, w.y);
            ffma2(acc[2], a1, w.x); ffma2(acc[3], a1, w.y);
        }
    }
}

static __device__ __forceinline__ void store_relu(float* __restrict__ sOut,
                                                  int r0, int colb, const u64 acc[4]) {
    float a, b, c, d;
    unpack2(acc[0], a, b); unpack2(acc[1], c, d);
    *(float4*)(sOut + r0*68 + colb) =
        make_float4(fmaxf(a,0.f), fmaxf(b,0.f), fmaxf(c,0.f), fmaxf(d,0.f));
    unpack2(acc[2], a, b); unpack2(acc[3], c, d);
    *(float4*)(sOut + (r0+4)*68 + colb) =
        make_float4(fmaxf(a,0.f), fmaxf(b,0.f), fmaxf(c,0.f), fmaxf(d,0.f));
}

// ---------------- combined node+edge MLP kernel (R3 champion version) ------
__global__ __launch_bounds__(256) void mlp_kernel(
    const float* __restrict__ node_enc, const float* __restrict__ edge_enc,
    const int* __restrict__ cni,
    const float* __restrict__ nW0, const float* __restrict__ nb0,
    const float* __restrict__ nW1, const float* __restrict__ nb1,
    const float* __restrict__ nW2, const float* __restrict__ nb2,
    const float* __restrict__ eW0, const float* __restrict__ eb0,
    const float* __restrict__ eW1, const float* __restrict__ eb1,
    const float* __restrict__ eW2, const float* __restrict__ eb2)
{
    // ---- role mapping (uniform across threads) ----
    int bid = blockIdx.x;
    int g = -1, chunk = 0, acc = 0, cnt = 0;
    bool isEdge = true;
    #pragma unroll
    for (int t = 0; t < NET; t++) {
        int n = g_ecnt[t];
        int c = (n + 31) >> 5;
        if (g < 0 && bid < acc + c) { g = t; chunk = bid - acc; cnt = n; }
        acc += c;
    }
    if (g < 0) {
        isEdge = false;
        int nb = bid - acc; acc = 0;
        #pragma unroll
        for (int t = 0; t < NT; t++) {
            int n = g_ncnt[t];
            int c = (n + 31) >> 5;
            if (g < 0 && nb < acc + c) { g = t; chunk = nb - acc; cnt = n; }
            acc += c;
        }
        if (g < 0) return;
    }
    int base  = chunk * 32;
    int ntask = min(32, cnt - base);

    __shared__ __align__(16) float sW[64*64];
    __shared__ __align__(16) float sb0[64], sb1[64], sb2[64];
    __shared__ __align__(16) float sA[32*68];
    __shared__ __align__(16) float sB[32*68];
    __shared__ int s_idx[32];
    __shared__ int s_off[32];

    int tid  = threadIdx.x;
    int warp = tid >> 5, lane = tid & 31;
    int colb = (warp & 1) * 32 + (lane & 7) * 4;
    int r0   = (warp >> 1) * 8 + (lane >> 3);

    const float *W0, *W1, *b0, *b1, *inBase;
    if (isEdge) {
        W0 = eW0 + g*4096; W1 = eW1 + g*4096;
        b0 = eb0 + g*64;   b1 = eb1 + g*64;
        inBase = edge_enc;
        if (tid < ntask) {
            int tt = g_ebucket[g*NETASK + base + tid];
            s_idx[tid] = tt;
            int b   = tt / (NC*3);
            int rem = tt - b*(NC*3);
            int c   = rem / 3;
            int p   = rem - 3*c;
            int a0  = (p == 2) ? 1 : 0;
            int a1  = (p == 0) ? 1 : 2;
            int i = clampi(cni[(b*NC + c)*3 + a0], 0, NA-1);
            int j = clampi(cni[(b*NC + c)*3 + a1], 0, NA-1);
            s_off[tid] = ((b*NA + i)*NA + j) * 64;
        }
    } else {
        W0 = nW0 + g*4096; W1 = nW1 + g*4096;
        b0 = nb0 + g*64;   b1 = nb1 + g*64;
        inBase = node_enc;
        if (tid < ntask) {
            int nn = g_nbucket[g*NNODE + base + tid];
            s_idx[tid] = nn;
            s_off[tid] = nn * 64;
        }
    }

    // stage W0 + biases
    {
        const float4* w = (const float4*)W0;
        float4* sw = (float4*)sW;
        #pragma unroll
        for (int k = 0; k < 4; k++) sw[tid + 256*k] = w[tid + 256*k];
        if (tid < 64) { sb0[tid] = b0[tid]; sb1[tid] = b1[tid]; }
    }
    __syncthreads();

    // gather inputs, prefetch W1 into regs
    float4 pw[4];
    {
        const float4* w = (const float4*)W1;
        #pragma unroll
        for (int k = 0; k < 4; k++) pw[k] = w[tid + 256*k];
    }
    for (int k = tid; k < ntask*16; k += 256) {
        int s = k >> 4, q = k & 15;
        float4 v = *(const float4*)(inBase + (size_t)s_off[s] + q*4);
        *(float4*)(sA + s*68 + q*4) = v;
    }
    __syncthreads();

    u64 a4[4];
    layer64(sA, sW, sb0, r0, colb, a4);          // layer 0
    __syncthreads();
    store_relu(sB, r0, colb, a4);
    {
        float4* sw = (float4*)sW;
        #pragma unroll
        for (int k = 0; k < 4; k++) sw[tid + 256*k] = pw[k];
    }
    if (isEdge) {
        const float4* w = (const float4*)(eW2 + g*4096);
        #pragma unroll
        for (int k = 0; k < 4; k++) pw[k] = w[tid + 256*k];
        if (tid < 64) sb2[tid] = eb2[g*64 + tid];
    } else {
        if (tid < 128) pw[0] = ((const float4*)(nW2 + g*512))[tid];
        if (tid < 8)   sb2[tid] = nb2[g*8 + tid];
    }
    __syncthreads();

    layer64(sB, sW, sb1, r0, colb, a4);          // layer 1
    __syncthreads();
    store_relu(sA, r0, colb, a4);
    {
        float4* sw = (float4*)sW;
        if (isEdge) {
            #pragma unroll
            for (int k = 0; k < 4; k++) sw[tid + 256*k] = pw[k];
        } else {
            if (tid < 128) sw[tid] = pw[0];
        }
    }
    __syncthreads();

    if (isEdge) {                                 // layer 2 (edge)
        layer64(sA, sW, sb2, r0, colb, a4);
        float a, b, c, d;
        if (r0 < ntask) {
            unpack2(a4[0], a, b); unpack2(a4[1], c, d);
            *(float4*)(g_ef + (size_t)s_idx[r0]*64 + colb) = make_float4(a, b, c, d);
        }
        if (r0 + 4 < ntask) {
            unpack2(a4[2], a, b); unpack2(a4[3], c, d);
            *(float4*)(g_ef + (size_t)s_idx[r0+4]*64 + colb) = make_float4(a, b, c, d);
        }
    } else {                                      // layer 2 (node, 64->8)
        int row = tid >> 3, col = tid & 7;
        float a = sb2[col];
        const float* in = sA + row*68;
        #pragma unroll 16
        for (int d = 0; d < 64; d++) a += in[d] * sW[d*8 + col];
        if (row < ntask) g_nf[(size_t)s_idx[row]*8 + col] = a;
    }
    __threadfence();
    cudaTriggerProgrammaticLaunchCompletion();
}

// ---------------- assemble: warp-per-clique, no block syncs (PDL) ----------
// grid 256 x 256: warp w of block b owns clique b*8+w. Private smem slab.
__global__ __launch_bounds__(256) void assemble_kernel(
    const int* __restrict__ cni, float* __restrict__ out, int writeZ)
{
    __shared__ float sE[8][192 + 8];     // per-warp e01|e02|e12 (+pad)
    __shared__ float sN[8][24 + 8];      // per-warp nf[3][8]

    int tid  = threadIdx.x;
    int warp = tid >> 5, lane = tid & 31;
    int cq   = blockIdx.x * 8 + warp;

    // PRE-SYNC: z tail (out region untouched by mlp)
    if (blockIdx.x == 0 && writeZ) {
        for (int m = tid; m < 512; m += 256) {
            int i = m >> 6, j = (m >> 3) & 7, k = m & 7;
            float* p = out + OUT_LOGPI + (size_t)m*3;
            p[0] = (float)i; p[1] = (float)j; p[2] = (float)k;
        }
    }
    // PRE-SYNC: node indices for this clique (cni is an input)
    int node_k = 0;
    if (lane < 24) {
        int k = lane >> 3;
        node_k = clampi(cni[cq*3 + k], 0, NA-1);
    }

    cudaGridDependencySynchronize();

    // post-sync: reset counters for next replay (block 0 only)
    if (blockIdx.x == 0) {
        if (tid < NET) g_ecnt[tid] = 0;
        if (tid < NT)  g_ncnt[tid] = 0;
    }

    // warp-private loads: 192 e floats (6 per lane, coalesced) + 24 nf
    size_t tbase = (size_t)cq * 192;
    #pragma unroll
    for (int k = 0; k < 6; k++)
        sE[warp][lane + 32*k] = __ldcg(&g_ef[tbase + lane + 32*k]);
    if (lane < 24) {
        int k = lane >> 3, zz = lane & 7;
        int b = cq >> 8;
        sN[warp][k*8 + zz] = __ldcg(&g_nf[((size_t)b*NA + node_k)*8 + zz]);
    }
    __syncwarp();

    // lane handles pairs p = lane and p = lane+32
    const float* e = sE[warp];
    const float* nf = sN[warp];
    #pragma unroll
    for (int half = 0; half < 2; half++) {
        int p  = lane + half*32;
        int z0 = p >> 3, z1 = p & 7;
        float bse = nf[z0] + nf[8 + z1] + e[p];
        float r[8];
        #pragma unroll
        for (int z2 = 0; z2 < 8; z2++)
            r[z2] = bse + nf[16 + z2] + e[64 + z0*8 + z2] + e[128 + z1*8 + z2];
        float* op = out + (size_t)cq*512 + p*8;
        *(float4*)op       = make_float4(r[0], r[1], r[2], r[3]);
        *(float4*)(op + 4) = make_float4(r[4], r[5], r[6], r[7]);
    }
}

// ---------------- launch ----------------
extern "C" void kernel_launch(void* const* d_in, const int* in_sizes, int n_in,
                              void* d_out, int out_size) {
    const int*   types    = (const int*)d_in[0];
    const float* node_enc = (const float*)d_in[1];
    const float* edge_enc = (const float*)d_in[2];
    const int*   cni      = (const int*)d_in[4];
    const float* nW0 = (const float*)d_in[6];
    const float* nb0 = (const float*)d_in[7];
    const float* nW1 = (const float*)d_in[8];
    const float* nb1 = (const float*)d_in[9];
    const float* nW2 = (const float*)d_in[10];
    const float* nb2 = (const float*)d_in[11];
    const float* eW0 = (const float*)d_in[12];
    const float* eb0 = (const float*)d_in[13];
    const float* eW1 = (const float*)d_in[14];
    const float* eb1 = (const float*)d_in[15];
    const float* eW2 = (const float*)d_in[16];
    const float* eb2 = (const float*)d_in[17];
    float* out = (float*)d_out;

    int writeZ = (out_size >= OUT_LOGPI + 512*3) ? 1 : 0;

    // plain launches for bin and mlp (bin->mlp overlap measured harmful 3x)
    bin_tasks_kernel<<<(NTASKS + 255) / 256, 256>>>(types, cni);
    mlp_kernel<<<240, 256>>>(node_enc, edge_enc, cni,
                             nW0, nb0, nW1, nb1, nW2, nb2,
                             eW0, eb0, eW1, eb1, eW2, eb2);

    // PDL on mlp->assemble (pre-sync work is tiny: z-tail + cni loads)
    cudaLaunchAttribute attr[1];
    attr[0].id = cudaLaunchAttributeProgrammaticStreamSerialization;
    attr[0].val.programmaticStreamSerializationAllowed = 1;
    cudaLaunchConfig_t cfg = {};
    cfg.gridDim  = dim3(BS * NC / 8, 1, 1);
    cfg.blockDim = dim3(256, 1, 1);
    cfg.stream   = 0;
    cfg.attrs    = attr;
    cfg.numAttrs = 1;
    cudaLaunchKernelEx(&cfg, assemble_kernel, cni, out, writeZ);
}